// round 17
// baseline (speedup 1.0000x reference)
#include <cuda_runtime.h>
#include <cstdint>

#define GRID_C 148

__device__ float G1d[2097152]; // [8192][256] = 1 - h1^2
__device__ float G2d[2097152]; // [8192][256] = 1 - h2^2
__device__ float W2P[65536];   // frag-permuted tf32 W2, ks-paired: [tt32][ksg16][lane][4]
__device__ float W1P[16384];   // frag-permuted tf32 W1, ks-paired: [jt8][ksg16][lane][4]
__device__ float W3P[16384];   // frag-permuted tf32 W3^T (A-side): [mt4][ks32][lane][4]

typedef unsigned long long u64;
__device__ __forceinline__ float rnaf(float f){
    uint32_t o; asm("cvt.rna.tf32.f32 %0, %1;" : "=r"(o) : "f"(f)); return __uint_as_float(o);
}
__device__ __forceinline__ u64 pk2(float s){ u64 r; asm("mov.b64 %0,{%1,%1};" : "=l"(r) : "f"(s)); return r; }
__device__ __forceinline__ u64 fma2(u64 a, u64 b, u64 c){ u64 d; asm("fma.rn.f32x2 %0,%1,%2,%3;" : "=l"(d) : "l"(a), "l"(b), "l"(c)); return d; }
__device__ __forceinline__ void mma8(float* c, const uint32_t* a, const uint32_t* b){
    asm volatile("mma.sync.aligned.m16n8k8.row.col.f32.tf32.tf32.f32 "
        "{%0,%1,%2,%3},{%4,%5,%6,%7},{%8,%9},{%0,%1,%2,%3};"
        : "+f"(c[0]), "+f"(c[1]), "+f"(c[2]), "+f"(c[3])
        : "r"(a[0]), "r"(a[1]), "r"(a[2]), "r"(a[3]), "r"(b[0]), "r"(b[1]));
}
#define CPA(dst, src) asm volatile("cp.async.cg.shared.global [%0],[%1],16;" :: "r"(dst), "l"(src) : "memory")
__device__ __forceinline__ uint32_t su32(const void* p){
    uint32_t a; asm("{.reg .u64 t; cvta.to.shared.u64 t,%1; cvt.u32.u64 %0,t;}" : "=r"(a) : "l"(p)); return a;
}

// ---------------- setup: prep (weight images) + fwd (exact g1/g2), one launch ----------------
__global__ void __launch_bounds__(256, 1) setup(const float* __restrict__ x,  const float* __restrict__ W1,
                                                const float* __restrict__ b1, const float* __restrict__ W2,
                                                const float* __restrict__ b2, const float* __restrict__ W3){
    {
        int i = blockIdx.x * blockDim.x + threadIdx.x, stride = gridDim.x * blockDim.x;
        for (int idx = i; idx < 65536; idx += stride){
            int w = idx & 3, lane = (idx >> 2) & 31, ksg = (idx >> 7) & 15, tt = idx >> 11;
            int ks = 2 * ksg + (w >> 1), reg = w & 1;
            int l = tt * 8 + (lane >> 2), k = ks * 8 + (lane & 3) + 4 * reg;
            W2P[idx] = rnaf(W2[l * 256 + k]);
        }
        for (int idx = i; idx < 16384; idx += stride){
            int w = idx & 3, lane = (idx >> 2) & 31, ksg = (idx >> 7) & 15, jt = idx >> 11;
            int ks = 2 * ksg + (w >> 1), reg = w & 1;
            int j = jt * 8 + (lane >> 2), ll = ks * 8 + (lane & 3) + 4 * reg;
            W1P[idx] = rnaf(W1[j * 256 + ll]);
        }
        for (int idx = i; idx < 16384; idx += stride){
            int w = idx & 3, lane = (idx >> 2) & 31, ks = (idx >> 7) & 31, mt = idx >> 12;
            int m = mt * 16 + (lane >> 2) + 8 * (w & 1);
            int k = ks * 8 + (lane & 3) + 4 * (w >> 1);
            W3P[idx] = rnaf(W3[k * 64 + m]);
        }
    }
    extern __shared__ float fs[];
    float* xs  = fs;             // [64 j][66]
    float* h1t = fs + 64 * 66;   // [256 l][66]
    const int t = threadIdx.x;
    const int b0 = blockIdx.x * 64;
    for (int r = 0; r < 16; r++){
        int idx = r * 256 + t, b = idx >> 6, j = idx & 63;
        xs[j * 66 + b] = x[(size_t)(b0 + b) * 64 + j];
    }
    __syncthreads();
    u64 acc[32];
    #pragma unroll
    for (int q = 0; q < 32; q++) acc[q] = 0ull;
    for (int j = 0; j < 64; j++){
        u64 wp = pk2(W1[j * 256 + t]);
        const u64* xr = (const u64*)(xs + j * 66);
        #pragma unroll
        for (int q = 0; q < 32; q++) acc[q] = fma2(xr[q], wp, acc[q]);
    }
    float bb = b1[t];
    #pragma unroll
    for (int q = 0; q < 32; q++){
        float2 f; asm("mov.b64 {%0,%1},%2;" : "=f"(f.x), "=f"(f.y) : "l"(acc[q]));
        float ha = tanhf(f.x + bb), hb = tanhf(f.y + bb);
        h1t[t * 66 + 2*q] = ha; h1t[t * 66 + 2*q + 1] = hb;
        G1d[(size_t)(b0 + 2*q) * 256 + t]     = 1.f - ha * ha;
        G1d[(size_t)(b0 + 2*q + 1) * 256 + t] = 1.f - hb * hb;
    }
    __syncthreads();
    #pragma unroll
    for (int q = 0; q < 32; q++) acc[q] = 0ull;
    for (int l = 0; l < 256; l++){
        u64 wp = pk2(W2[l * 256 + t]);
        const u64* hr = (const u64*)(h1t + l * 66);
        #pragma unroll
        for (int q = 0; q < 32; q++) acc[q] = fma2(hr[q], wp, acc[q]);
    }
    bb = b2[t];
    #pragma unroll
    for (int q = 0; q < 32; q++){
        float2 f; asm("mov.b64 {%0,%1},%2;" : "=f"(f.x), "=f"(f.y) : "l"(acc[q]));
        float ha = tanhf(f.x + bb), hb = tanhf(f.y + bb);
        G2d[(size_t)(b0 + 2*q) * 256 + t]     = 1.f - ha * ha;
        G2d[(size_t)(b0 + 2*q + 1) * 256 + t] = 1.f - hb * hb;
    }
}

// ---------------- jmain: 256 thr, 4 batches/CTA, m16-stage software pipeline ----------------
// smem floats: W3s 16384 | C1B 2 x (4 x 4096) | g2q 2x1024(parity)
#define SMF (16384 + 32768 + 2048)

// GEMM1 one m16 stage into C1r[4][4][4]
__device__ __forceinline__ void g1_stage(float C1r[4][4][4], int mt,
                                         const float4* W3s4, const float4* B1p, const float4* gq4,
                                         int lane, int tg, int wid){
    #pragma unroll 2
    for (int ksg = 0; ksg < 16; ksg++){
        float4 Ae = W3s4[(mt * 32 + 2 * ksg)     * 32 + lane];
        float4 Ao = W3s4[(mt * 32 + 2 * ksg + 1) * 32 + lane];
        float4 Bf[4];
        #pragma unroll
        for (int f = 0; f < 4; f++)
            Bf[f] = B1p[((4 * wid + f) * 16 + ksg) * 32 + lane];
        float4 gq[4];
        #pragma unroll
        for (int b = 0; b < 4; b++) gq[b] = gq4[b * 64 + ksg * 4 + tg];
        #pragma unroll
        for (int b = 0; b < 4; b++)
            #pragma unroll
            for (int f = 0; f < 4; f++){
                float2 Se, So;
                Se.x = rnaf(Bf[f].x * gq[b].x); Se.y = rnaf(Bf[f].y * gq[b].y);
                So.x = rnaf(Bf[f].z * gq[b].z); So.y = rnaf(Bf[f].w * gq[b].w);
                mma8(C1r[b][f], (const uint32_t*)&Ae, (const uint32_t*)&Se);
                mma8(C1r[b][f], (const uint32_t*)&Ao, (const uint32_t*)&So);
            }
    }
}

// fused: GEMM1 stage mt + GEMM2 from rbuf (both per-ksg, interleaved for the scheduler)
__device__ __forceinline__ void fused_stage(float C1r[4][4][4], int mt, float J[4][4],
                                            const float4* W3s4, const float4* B1p, const float4* gq4,
                                            const float4* A2b4, const float4* B2p,
                                            int lane, int tg, int wid, int nh, int idxA){
    #pragma unroll 2
    for (int ksg = 0; ksg < 16; ksg++){
        float4 Ae = W3s4[(mt * 32 + 2 * ksg)     * 32 + lane];
        float4 Ao = W3s4[(mt * 32 + 2 * ksg + 1) * 32 + lane];
        float4 A2e = A2b4[(2 * ksg)     * 32 + idxA];
        float4 A2o = A2b4[(2 * ksg + 1) * 32 + idxA];
        float4 Bf[4];
        #pragma unroll
        for (int f = 0; f < 4; f++)
            Bf[f] = B1p[((4 * wid + f) * 16 + ksg) * 32 + lane];
        float4 gq[4];
        #pragma unroll
        for (int b = 0; b < 4; b++) gq[b] = gq4[b * 64 + ksg * 4 + tg];
        #pragma unroll
        for (int b = 0; b < 4; b++)
            #pragma unroll
            for (int f = 0; f < 4; f++){
                float2 Se, So;
                Se.x = rnaf(Bf[f].x * gq[b].x); Se.y = rnaf(Bf[f].y * gq[b].y);
                So.x = rnaf(Bf[f].z * gq[b].z); So.y = rnaf(Bf[f].w * gq[b].w);
                mma8(C1r[b][f], (const uint32_t*)&Ae, (const uint32_t*)&Se);
                mma8(C1r[b][f], (const uint32_t*)&Ao, (const uint32_t*)&So);
            }
        #pragma unroll
        for (int f = 0; f < 4; f++){
            float4 Bv = B2p[((nh * 4 + f) * 16 + ksg) * 32 + lane];
            float2 Be = make_float2(Bv.x, Bv.y);
            float2 Bo = make_float2(Bv.z, Bv.w);
            mma8(J[f], (const uint32_t*)&A2e, (const uint32_t*)&Be);
            mma8(J[f], (const uint32_t*)&A2o, (const uint32_t*)&Bo);
        }
    }
}

// GEMM2 only (tail)
__device__ __forceinline__ void g2_stage(float J[4][4], const float4* A2b4, const float4* B2p,
                                         int lane, int nh, int idxA){
    #pragma unroll 2
    for (int ksg = 0; ksg < 16; ksg++){
        float4 A2e = A2b4[(2 * ksg)     * 32 + idxA];
        float4 A2o = A2b4[(2 * ksg + 1) * 32 + idxA];
        #pragma unroll
        for (int f = 0; f < 4; f++){
            float4 Bv = B2p[((nh * 4 + f) * 16 + ksg) * 32 + lane];
            float2 Be = make_float2(Bv.x, Bv.y);
            float2 Bo = make_float2(Bv.z, Bv.w);
            mma8(J[f], (const uint32_t*)&A2e, (const uint32_t*)&Be);
            mma8(J[f], (const uint32_t*)&A2o, (const uint32_t*)&Bo);
        }
    }
}

__device__ __forceinline__ void park_stage(const float C1r[4][4][4], float* Cbuf,
                                           const float* g1base, int wid, int tg, int g,
                                           int ca, int cb, int wa){
    #pragma unroll
    for (int b = 0; b < 4; b++){
        float* C1w = Cbuf + b * 4096;
        const float* g1b = g1base + (size_t)b * 256;
        #pragma unroll
        for (int f = 0; f < 4; f++){
            const int ss = 4 * wid + f;
            const float gv0 = __ldg(g1b + ss * 8 + 2 * tg);
            const float gv1 = __ldg(g1b + ss * 8 + 2 * tg + 1);
            float2 v0, v1;
            v0.x = rnaf(C1r[b][f][0] * gv0); v0.y = rnaf(C1r[b][f][2] * gv0);
            v1.x = rnaf(C1r[b][f][1] * gv1); v1.y = rnaf(C1r[b][f][3] * gv1);
            *(float2*)&C1w[(ss * 32 + ca * 8 + g) * 4 + wa] = v0;
            *(float2*)&C1w[(ss * 32 + cb * 8 + g) * 4 + wa] = v1;
        }
    }
}

__device__ __forceinline__ void epi_stage(const float J[4][4], float* ob, int st,
                                          int g, int tg, int nh){
    const int r0 = st * 16 + g;
    #pragma unroll
    for (int f = 0; f < 4; f++){
        const int cc = (nh * 4 + f) * 8 + 2 * tg;
        *(float2*)(ob + (size_t)r0 * 64 + cc)       = make_float2(J[f][0], J[f][1]);
        *(float2*)(ob + (size_t)(r0 + 8) * 64 + cc) = make_float2(J[f][2], J[f][3]);
    }
}

__global__ void __launch_bounds__(256, 1) jmain(float* __restrict__ out){
    extern __shared__ float s[];
    float* W3s = s;                 // 16384
    float* C1B = s + 16384;         // 2 x (4 x 4096) m16-stage double buffer
    float* g2q = C1B + 32768;       // 2 x 1024 (parity float4 quads)

    const int t = threadIdx.x, lane = t & 31, wid = t >> 5;   // wid 0..7
    const int g = lane >> 2, tg = lane & 3;
    const uint32_t w3sb = su32(W3s);

    #pragma unroll
    for (int i = 0; i < 16; i++){
        int u = t + i * 256;
        CPA(w3sb + (uint32_t)u * 16, (const char*)W3P + u * 16);
    }
    asm volatile("cp.async.commit_group;\ncp.async.wait_group 0;" ::: "memory");
    __syncthreads();

    const float4* W3s4 = (const float4*)W3s;
    const float4* B1p  = (const float4*)W2P;
    const float4* B2p  = (const float4*)W1P;

    const int bq = wid & 3, nh = wid >> 2;
    const int idxA = tg * 8 + g;
    const int ca = (2 * tg) & 3, wa = 2 * ((2 * tg) >> 2);
    const int cb = (2 * tg + 1) & 3;

    int it = 0;
    for (int p = blockIdx.x; p < 2048; p += GRID_C, it ^= 1){
        {
            const int b = t >> 6, e = t & 63;
            const size_t base = (size_t)(4 * p + b) * 256 + 16 * (e >> 2) + (e & 3);
            float4 v;
            v.x = G2d[base]; v.y = G2d[base + 4]; v.z = G2d[base + 8]; v.w = G2d[base + 12];
            ((float4*)g2q)[it * 256 + t] = v;
        }
        __syncthreads();
        const float4* gq4 = (const float4*)g2q + it * 256;
        const float* g1base = G1d + (size_t)(4 * p) * 256;
        float* ob = out + (size_t)(4 * p + bq) * 4096;

        // prologue: stage 0
        {
            float C1r[4][4][4];
            #pragma unroll
            for (int b = 0; b < 4; b++)
                #pragma unroll
                for (int f = 0; f < 4; f++)
                    #pragma unroll
                    for (int q = 0; q < 4; q++) C1r[b][f][q] = 0.f;
            g1_stage(C1r, 0, W3s4, B1p, gq4, lane, tg, wid);
            park_stage(C1r, C1B, g1base, wid, tg, g, ca, cb, wa);
        }
        __syncthreads();

        // pipelined stages s = 0..2
        #pragma unroll 1
        for (int sidx = 0; sidx < 3; sidx++){
            float C1r[4][4][4];
            float J[4][4];
            #pragma unroll
            for (int b = 0; b < 4; b++)
                #pragma unroll
                for (int f = 0; f < 4; f++)
                    #pragma unroll
                    for (int q = 0; q < 4; q++) C1r[b][f][q] = 0.f;
            #pragma unroll
            for (int f = 0; f < 4; f++)
                #pragma unroll
                for (int q = 0; q < 4; q++) J[f][q] = 0.f;

            const float4* A2b4 = (const float4*)(C1B + (sidx & 1) * 16384 + bq * 4096);
            fused_stage(C1r, sidx + 1, J, W3s4, B1p, gq4, A2b4, B2p, lane, tg, wid, nh, idxA);
            park_stage(C1r, C1B + ((sidx + 1) & 1) * 16384, g1base, wid, tg, g, ca, cb, wa);
            epi_stage(J, ob, sidx, g, tg, nh);
            __syncthreads();
        }

        // tail: stage 3 GEMM2 from buf1
        {
            float J[4][4];
            #pragma unroll
            for (int f = 0; f < 4; f++)
                #pragma unroll
                for (int q = 0; q < 4; q++) J[f][q] = 0.f;
            const float4* A2b4 = (const float4*)(C1B + 16384 + bq * 4096);
            g2_stage(J, A2b4, B2p, lane, nh, idxA);
            epi_stage(J, ob, 3, g, tg, nh);
        }
    }
}

extern "C" void kernel_launch(void* const* d_in, const int* in_sizes, int n_in,
                              void* d_out, int out_size)
{
    const float* x  = (const float*)d_in[0];
    const float* W1 = (const float*)d_in[1];
    const float* b1 = (const float*)d_in[2];
    const float* W2 = (const float*)d_in[3];
    const float* b2 = (const float*)d_in[4];
    const float* W3 = (const float*)d_in[5];
    float* out = (float*)d_out;

    cudaFuncSetAttribute(setup, cudaFuncAttributeMaxDynamicSharedMemorySize, (64*66 + 256*66) * 4);
    cudaFuncSetAttribute(jmain, cudaFuncAttributeMaxDynamicSharedMemorySize, SMF * 4);

    setup<<<128, 256, (64*66 + 256*66) * 4>>>(x, W1, b1, W2, b2, W3);
    jmain<<<GRID_C, 256, SMF * 4>>>(out);
}